// round 2
// baseline (speedup 1.0000x reference)
#include <cuda_runtime.h>

typedef unsigned long long u64;

#define B_ 4096
#define T_ 128
#define I_ 16
#define H_ 64
#define NT 96    // threads per block: each thread owns gate-rows (tid, tid+96)

// ---- packed f32x2 helpers (sm_100+; ptxas never emits these from C++) ----
__device__ __forceinline__ u64 pk2(float lo, float hi) {
    u64 r; asm("mov.b64 %0, {%1,%2};" : "=l"(r) : "f"(lo), "f"(hi)); return r;
}
__device__ __forceinline__ void upk2(u64 v, float& lo, float& hi) {
    asm("mov.b64 {%0,%1}, %2;" : "=f"(lo), "=f"(hi) : "l"(v));
}
__device__ __forceinline__ u64 fma2(u64 a, u64 b, u64 c) {
    u64 d; asm("fma.rn.f32x2 %0, %1, %2, %3;" : "=l"(d) : "l"(a), "l"(b), "l"(c)); return d;
}
__device__ __forceinline__ u64 add2(u64 a, u64 b) {
    u64 d; asm("add.rn.f32x2 %0, %1, %2;" : "=l"(d) : "l"(a), "l"(b)); return d;
}
__device__ __forceinline__ float red2(u64 v) { float lo, hi; upk2(v, lo, hi); return lo + hi; }

// exp-based activations (~1e-6/step error; tanh.approx's 2^-11 would compound)
__device__ __forceinline__ float sigmoidf_(float a) { return __fdividef(1.0f, 1.0f + __expf(-a)); }
__device__ __forceinline__ float tanhf_(float a)    { return __fdividef(2.0f, 1.0f + __expf(-2.0f * a)) - 1.0f; }

__global__ void __launch_bounds__(NT, 4) gru_tg2_kernel(
    const float* __restrict__ x,     // [B, T, I]
    const float* __restrict__ w_ih,  // [3H, I]
    const float* __restrict__ w_hh,  // [3H, H]
    const float* __restrict__ b_ih,  // [3H]
    const float* __restrict__ b_hh,  // [3H]
    const float* __restrict__ fc_w,  // [1, H]
    const float* __restrict__ fc_b,  // [1]
    float* __restrict__ out)         // [B]
{
    __shared__ __align__(16) u64   sx[T_ * I_ / 2];  // 8 KB: this batch's x, f32x2 pairs
    __shared__ __align__(16) float shf[H_];          // hidden state
    __shared__ float sA[3 * H_];                     // per-row: sigma(r/z) or xa_n
    __shared__ float sHn[H_];                        // ha for n-rows
    __shared__ float sBi[3 * H_], sBh[3 * H_];       // biases (keep out of registers)

    const int tid = threadIdx.x;     // 0..95
    const int b   = blockIdx.x;      // batch element
    const int ga  = tid;             // row a: 0..95   (always r or z)
    const int gb  = tid + NT;        // row b: 96..191 (z for tid<32, else n)

    // ---- preload x slice (coalesced, 8 KB) ----
    const u64* gx = reinterpret_cast<const u64*>(x + (size_t)b * (T_ * I_));
    for (int i = tid; i < T_ * I_ / 2; i += NT) sx[i] = gx[i];
    if (tid < H_) shf[tid] = 0.0f;   // h0 = 0
    sBi[ga] = b_ih[ga]; sBi[gb] = b_ih[gb];
    sBh[ga] = b_hh[ga]; sBh[gb] = b_hh[gb];

    // ---- register-resident weights for 2 gate-rows (k-packed f32x2) ----
    u64 wha[H_ / 2], whb[H_ / 2];    // 2 x 32 u64 = 128 regs
    {
        const u64* ra = reinterpret_cast<const u64*>(w_hh + ga * H_);
        const u64* rb = reinterpret_cast<const u64*>(w_hh + gb * H_);
        #pragma unroll
        for (int k = 0; k < H_ / 2; k++) { wha[k] = ra[k]; whb[k] = rb[k]; }
    }
    u64 wia[I_ / 2], wib[I_ / 2];    // 2 x 8 u64 = 16 regs
    {
        const u64* ia = reinterpret_cast<const u64*>(w_ih + ga * I_);
        const u64* ib = reinterpret_cast<const u64*>(w_ih + gb * I_);
        #pragma unroll
        for (int k = 0; k < I_ / 2; k++) { wia[k] = ia[k]; wib[k] = ib[k]; }
    }
    __syncthreads();

    const ulonglong2* sh4 = reinterpret_cast<const ulonglong2*>(shf);

    for (int t = 0; t < T_; t++) {
        // ---- x-part for both rows (x_t read ONCE, feeds 2 rows) ----
        const ulonglong2* xt = reinterpret_cast<const ulonglong2*>(sx + t * (I_ / 2));
        u64 xaacc = pk2(sBi[ga], 0.0f);
        u64 xbacc = pk2(sBi[gb], 0.0f);
        #pragma unroll
        for (int m = 0; m < I_ / 4; m++) {           // 4 iters
            ulonglong2 v = xt[m];                    // LDS.128 broadcast
            xaacc = fma2(wia[2 * m + 0], v.x, xaacc);
            xbacc = fma2(wib[2 * m + 0], v.x, xbacc);
            xaacc = fma2(wia[2 * m + 1], v.y, xaacc);
            xbacc = fma2(wib[2 * m + 1], v.y, xbacc);
        }

        // ---- h-part: each 16B of h feeds 4 FFMA2 (2 rows), 4 chains total ----
        u64 a0 = pk2(sBh[ga], 0.0f), a1 = pk2(0.0f, 0.0f);
        u64 b0 = pk2(sBh[gb], 0.0f), b1 = pk2(0.0f, 0.0f);
        #pragma unroll
        for (int m = 0; m < H_ / 8; m++) {           // 8 iters, 8 FFMA2 each
            ulonglong2 v0 = sh4[2 * m + 0];          // LDS.128 broadcast
            ulonglong2 v1 = sh4[2 * m + 1];
            a0 = fma2(wha[4 * m + 0], v0.x, a0);
            b0 = fma2(whb[4 * m + 0], v0.x, b0);
            a1 = fma2(wha[4 * m + 1], v0.y, a1);
            b1 = fma2(whb[4 * m + 1], v0.y, b1);
            a0 = fma2(wha[4 * m + 2], v1.x, a0);
            b0 = fma2(whb[4 * m + 2], v1.x, b0);
            a1 = fma2(wha[4 * m + 3], v1.y, a1);
            b1 = fma2(whb[4 * m + 3], v1.y, b1);
        }
        const float xa = red2(xaacc);
        const float xb = red2(xbacc);
        const float ha = red2(add2(a0, a1));
        const float hb = red2(add2(b0, b1));

        // ---- publish: r/z rows store sigma(xa+ha); n rows store (xa, ha) ----
        sA[ga] = sigmoidf_(xa + ha);                 // ga < 128 always
        if (gb < 2 * H_) sA[gb] = sigmoidf_(xb + hb);
        else             { sA[gb] = xb; sHn[gb - 2 * H_] = hb; }
        __syncthreads();

        // ---- elementwise state update (threads 0..63) ----
        if (tid < H_) {
            float r = sA[tid];
            float z = sA[tid + H_];
            float n = tanhf_(sA[tid + 2 * H_] + r * sHn[tid]);
            float h = shf[tid];
            shf[tid] = n + z * (h - n);              // (1-z)*n + z*h
        }
        __syncthreads();
    }

    // ---- linear head ----
    if (tid < H_) sA[tid] = shf[tid] * fc_w[tid];
    __syncthreads();
    if (tid == 0) {
        float s = fc_b[0];
        #pragma unroll
        for (int k = 0; k < H_; k++) s += sA[k];
        out[b] = s;
    }
}

extern "C" void kernel_launch(void* const* d_in, const int* in_sizes, int n_in,
                              void* d_out, int out_size) {
    const float* x    = (const float*)d_in[0];
    const float* w_ih = (const float*)d_in[1];
    const float* w_hh = (const float*)d_in[2];
    const float* b_ih = (const float*)d_in[3];
    const float* b_hh = (const float*)d_in[4];
    const float* fc_w = (const float*)d_in[5];
    const float* fc_b = (const float*)d_in[6];
    float* out = (float*)d_out;

    gru_tg2_kernel<<<B_, NT>>>(x, w_ih, w_hh, b_ih, b_hh, fc_w, fc_b, out);
}

// round 4
// speedup vs baseline: 1.4791x; 1.4791x over previous
#include <cuda_runtime.h>

typedef unsigned long long u64;

#define B_ 4096
#define T_ 128
#define I_ 16
#define H_ 64
#define G3_ 192   // 3*H gate rows
#define NT 96     // recurrent kernel threads: thread owns rows (tid, tid+96)

// 402 MB scratch for precomputed input projections gi[b][t][g]
__device__ float g_gi[(size_t)B_ * T_ * G3_];

// ---- packed f32x2 helpers (sm_100+; ptxas never emits these from C++) ----
__device__ __forceinline__ u64 pk2(float lo, float hi) {
    u64 r; asm("mov.b64 %0, {%1,%2};" : "=l"(r) : "f"(lo), "f"(hi)); return r;
}
__device__ __forceinline__ void upk2(u64 v, float& lo, float& hi) {
    asm("mov.b64 {%0,%1}, %2;" : "=f"(lo), "=f"(hi) : "l"(v));
}
__device__ __forceinline__ u64 fma2(u64 a, u64 b, u64 c) {
    u64 d; asm("fma.rn.f32x2 %0, %1, %2, %3;" : "=l"(d) : "l"(a), "l"(b), "l"(c)); return d;
}
__device__ __forceinline__ u64 add2(u64 a, u64 b) {
    u64 d; asm("add.rn.f32x2 %0, %1, %2;" : "=l"(d) : "l"(a), "l"(b)); return d;
}
__device__ __forceinline__ float red2(u64 v) { float lo, hi; upk2(v, lo, hi); return lo + hi; }

// exp-based activations (~1e-6/step; tanh.approx's 2^-11 would compound over T=128)
__device__ __forceinline__ float sigmoidf_(float a) { return __fdividef(1.0f, 1.0f + __expf(-a)); }
__device__ __forceinline__ float tanhf_(float a)    { return __fdividef(2.0f, 1.0f + __expf(-2.0f * a)) - 1.0f; }

// ============================================================================
// Pass 1: gi[b,t,g] = w_ih[g,:]·x[b,t,:] + b_ih[g] + (g<2H ? b_hh[g] : 0)
// ============================================================================
__global__ __launch_bounds__(G3_) void gru_xproj_kernel(
    const float* __restrict__ x,     // [B, T, I]
    const float* __restrict__ w_ih,  // [3H, I]
    const float* __restrict__ b_ih,  // [3H]
    const float* __restrict__ b_hh)  // [3H]
{
    __shared__ __align__(16) u64 sx[T_ * I_ / 2];   // 8 KB
    const int g = threadIdx.x;
    const int b = blockIdx.x;

    const u64* gx = reinterpret_cast<const u64*>(x + (size_t)b * (T_ * I_));
    for (int i = g; i < T_ * I_ / 2; i += G3_) sx[i] = gx[i];

    u64 wi[I_ / 2];
    const u64* wr = reinterpret_cast<const u64*>(w_ih + g * I_);
    #pragma unroll
    for (int k = 0; k < I_ / 2; k++) wi[k] = wr[k];
    const float bias = b_ih[g] + ((g < 2 * H_) ? b_hh[g] : 0.0f);

    __syncthreads();

    float* gout = g_gi + (size_t)b * (T_ * G3_) + g;
    #pragma unroll 4
    for (int t = 0; t < T_; t++) {
        const ulonglong2* xt = reinterpret_cast<const ulonglong2*>(sx + t * (I_ / 2));
        u64 a0 = pk2(bias, 0.0f), a1 = pk2(0.0f, 0.0f);
        #pragma unroll
        for (int m = 0; m < I_ / 4; m++) {
            ulonglong2 v = xt[m];
            a0 = fma2(wi[2 * m + 0], v.x, a0);
            a1 = fma2(wi[2 * m + 1], v.y, a1);
        }
        gout[t * G3_] = red2(add2(a0, a1));
    }
}

// ============================================================================
// Pass 2: recurrence. Thread owns gate-rows (tid, tid+96); w_hh register-resident.
// ============================================================================
__global__ void __launch_bounds__(NT, 3) gru_rec_kernel(
    const float* __restrict__ w_hh,  // [3H, H]
    const float* __restrict__ b_hh,  // [3H]
    const float* __restrict__ fc_w,  // [1, H]
    const float* __restrict__ fc_b,  // [1]
    float* __restrict__ out)         // [B]
{
    __shared__ __align__(16) float shf[H_];   // hidden state
    __shared__ float sA[G3_];                 // r,z (sigmoided) and gi_n
    __shared__ float sHn[H_];                 // recurrent part for n rows

    const int tid = threadIdx.x;     // 0..95
    const int b   = blockIdx.x;
    const int ga  = tid;             // rows 0..95   (r rows 0-63, z rows 64-95)
    const int gb  = tid + NT;        // rows 96..191 (z rows 96-127, n rows 128-191)

    // register-resident w_hh for both rows (k-packed f32x2): 128 regs
    u64 wha[H_ / 2], whb[H_ / 2];
    {
        const u64* ra = reinterpret_cast<const u64*>(w_hh + ga * H_);
        const u64* rb = reinterpret_cast<const u64*>(w_hh + gb * H_);
        #pragma unroll
        for (int k = 0; k < H_ / 2; k++) { wha[k] = ra[k]; whb[k] = rb[k]; }
    }
    const float bhb = (tid < 32) ? 0.0f : b_hh[gb];   // b_hh folded into gi for r/z

    if (tid < H_) shf[tid] = 0.0f;

    const float* gbase = g_gi + (size_t)b * (T_ * G3_);
    // prefetch ring, distance 2
    float pga[2], pgb[2];
    pga[0] = gbase[ga];          pgb[0] = gbase[gb];
    pga[1] = gbase[G3_ + ga];    pgb[1] = gbase[G3_ + gb];

    __syncthreads();

    const ulonglong2* sh4 = reinterpret_cast<const ulonglong2*>(shf);

    #pragma unroll 2
    for (int t = 0; t < T_; t++) {
        const float gia = pga[t & 1];
        const float gib = pgb[t & 1];
        const int tn = t + 2;
        if (tn < T_) {
            pga[t & 1] = gbase[tn * G3_ + ga];
            pgb[t & 1] = gbase[tn * G3_ + gb];
        }

        // h-part for both rows: 4 chains, 8 FFMA2 per 32B of h
        u64 a0 = pk2(0.0f, 0.0f), a1 = pk2(0.0f, 0.0f);
        u64 c0 = pk2(bhb, 0.0f),  c1 = pk2(0.0f, 0.0f);
        #pragma unroll
        for (int m = 0; m < H_ / 8; m++) {
            ulonglong2 v0 = sh4[2 * m + 0];   // LDS.128 uniform broadcast
            ulonglong2 v1 = sh4[2 * m + 1];
            a0 = fma2(wha[4 * m + 0], v0.x, a0);
            c0 = fma2(whb[4 * m + 0], v0.x, c0);
            a1 = fma2(wha[4 * m + 1], v0.y, a1);
            c1 = fma2(whb[4 * m + 1], v0.y, c1);
            a0 = fma2(wha[4 * m + 2], v1.x, a0);
            c0 = fma2(whb[4 * m + 2], v1.x, c0);
            a1 = fma2(wha[4 * m + 3], v1.y, a1);
            c1 = fma2(whb[4 * m + 3], v1.y, c1);
        }
        const float ha = red2(add2(a0, a1));
        const float hb = red2(add2(c0, c1));

        // publish
        sA[ga] = sigmoidf_(gia + ha);                      // r or z rows
        if (tid < 32) sA[gb] = sigmoidf_(gib + hb);        // z rows 96..127
        else          { sA[gb] = gib; sHn[tid - 32] = hb; }// n rows: keep parts
        __syncthreads();

        // elementwise state update (threads 0..63)
        if (tid < H_) {
            float r  = sA[tid];
            float z  = sA[tid + H_];
            float n  = tanhf_(sA[tid + 2 * H_] + r * sHn[tid]);
            float h  = shf[tid];
            shf[tid] = n + z * (h - n);                    // (1-z)*n + z*h
        }
        __syncthreads();
    }

    // linear head
    if (tid < H_) sA[tid] = shf[tid] * fc_w[tid];
    __syncthreads();
    if (tid == 0) {
        float s = fc_b[0];
        #pragma unroll
        for (int k = 0; k < H_; k++) s += sA[k];
        out[b] = s;
    }
}

extern "C" void kernel_launch(void* const* d_in, const int* in_sizes, int n_in,
                              void* d_out, int out_size) {
    const float* x    = (const float*)d_in[0];
    const float* w_ih = (const float*)d_in[1];
    const float* w_hh = (const float*)d_in[2];
    const float* b_ih = (const float*)d_in[3];
    const float* b_hh = (const float*)d_in[4];
    const float* fc_w = (const float*)d_in[5];
    const float* fc_b = (const float*)d_in[6];
    float* out = (float*)d_out;

    gru_xproj_kernel<<<B_, G3_>>>(x, w_ih, b_ih, b_hh);
    gru_rec_kernel<<<B_, NT>>>(w_hh, b_hh, fc_w, fc_b, out);
}

// round 5
// speedup vs baseline: 1.5459x; 1.0451x over previous
#include <cuda_runtime.h>

typedef unsigned long long u64;

#define B_ 4096
#define T_ 128
#define I_ 16
#define H_ 64
#define G3_ 192   // 3*H gate rows

// 402 MB scratch for precomputed input projections gi[b][t][g]
__device__ float g_gi[(size_t)B_ * T_ * G3_];

// ---- packed f32x2 helpers (sm_100+; ptxas never emits these from C++) ----
__device__ __forceinline__ u64 pk2(float lo, float hi) {
    u64 r; asm("mov.b64 %0, {%1,%2};" : "=l"(r) : "f"(lo), "f"(hi)); return r;
}
__device__ __forceinline__ void upk2(u64 v, float& lo, float& hi) {
    asm("mov.b64 {%0,%1}, %2;" : "=f"(lo), "=f"(hi) : "l"(v));
}
__device__ __forceinline__ u64 fma2(u64 a, u64 b, u64 c) {
    u64 d; asm("fma.rn.f32x2 %0, %1, %2, %3;" : "=l"(d) : "l"(a), "l"(b), "l"(c)); return d;
}
__device__ __forceinline__ u64 add2(u64 a, u64 b) {
    u64 d; asm("add.rn.f32x2 %0, %1, %2;" : "=l"(d) : "l"(a), "l"(b)); return d;
}
__device__ __forceinline__ float red2(u64 v) { float lo, hi; upk2(v, lo, hi); return lo + hi; }
__device__ __forceinline__ u64 shflx16(u64 v) { return __shfl_xor_sync(0xFFFFFFFFu, v, 16); }

// exp-based activations (~1e-6/step; tanh.approx's 2^-11 would compound over T=128)
__device__ __forceinline__ float sigmoidf_(float a) { return __fdividef(1.0f, 1.0f + __expf(-a)); }
__device__ __forceinline__ float tanhf_(float a)    { return __fdividef(2.0f, 1.0f + __expf(-2.0f * a)) - 1.0f; }

// ============================================================================
// Pass 1: gi[b,t,g] = w_ih[g,:]·x[b,t,:] + b_ih[g] + (g<2H ? b_hh[g] : 0)
// ============================================================================
__global__ __launch_bounds__(G3_) void gru_xproj_kernel(
    const float* __restrict__ x,     // [B, T, I]
    const float* __restrict__ w_ih,  // [3H, I]
    const float* __restrict__ b_ih,  // [3H]
    const float* __restrict__ b_hh)  // [3H]
{
    __shared__ __align__(16) u64 sx[T_ * I_ / 2];   // 8 KB
    const int g = threadIdx.x;
    const int b = blockIdx.x;

    const u64* gx = reinterpret_cast<const u64*>(x + (size_t)b * (T_ * I_));
    for (int i = g; i < T_ * I_ / 2; i += G3_) sx[i] = gx[i];

    u64 wi[I_ / 2];
    const u64* wr = reinterpret_cast<const u64*>(w_ih + g * I_);
    #pragma unroll
    for (int k = 0; k < I_ / 2; k++) wi[k] = wr[k];
    const float bias = b_ih[g] + ((g < 2 * H_) ? b_hh[g] : 0.0f);

    __syncthreads();

    float* gout = g_gi + (size_t)b * (T_ * G3_) + g;
    #pragma unroll 4
    for (int t = 0; t < T_; t++) {
        const ulonglong2* xt = reinterpret_cast<const ulonglong2*>(sx + t * (I_ / 2));
        u64 a0 = pk2(bias, 0.0f), a1 = pk2(0.0f, 0.0f);
        #pragma unroll
        for (int m = 0; m < I_ / 4; m++) {
            ulonglong2 v = xt[m];
            a0 = fma2(wi[2 * m + 0], v.x, a0);
            a1 = fma2(wi[2 * m + 1], v.y, a1);
        }
        gout[t * G3_] = red2(add2(a0, a1));
    }
}

// ============================================================================
// Pass 2: recurrence. Thread (warp w, lane l) owns hidden unit j = w*16+(l&15),
// k-half s = l>>4. All 3 gates of unit j computed locally; partial K-sums
// combined with shfl.bfly(16). One barrier per step via double-buffered h.
// ============================================================================
#define NT2 128
__global__ void __launch_bounds__(NT2, 3) gru_rec_kernel(
    const float* __restrict__ w_hh,  // [3H, H]
    const float* __restrict__ b_hh,  // [3H]
    const float* __restrict__ fc_w,  // [1, H]
    const float* __restrict__ fc_b,  // [1]
    float* __restrict__ out)         // [B]
{
    __shared__ __align__(16) float hbuf[2][H_];   // double-buffered hidden state
    __shared__ float sred[H_];

    const int tid  = threadIdx.x;
    const int b    = blockIdx.x;
    const int lane = tid & 31;
    const int wrp  = tid >> 5;
    const int j    = wrp * 16 + (lane & 15);   // hidden unit 0..63
    const int s    = lane >> 4;                // k-half: [32s, 32s+32)

    // register-resident w_hh for rows (j, j+64, j+128), this thread's k-half
    u64 wr_[16], wz_[16], wn_[16];             // 48 u64 = 96 regs
    {
        const u64* pr = reinterpret_cast<const u64*>(w_hh + (j          ) * H_ + s * 32);
        const u64* pz = reinterpret_cast<const u64*>(w_hh + (j +     H_ ) * H_ + s * 32);
        const u64* pn = reinterpret_cast<const u64*>(w_hh + (j + 2 * H_ ) * H_ + s * 32);
        #pragma unroll
        for (int k = 0; k < 16; k++) { wr_[k] = pr[k]; wz_[k] = pz[k]; wn_[k] = pn[k]; }
    }
    const float bhn = (s == 0) ? b_hh[j + 2 * H_] : 0.0f;  // n-row bias, one half only

    if (tid < H_) hbuf[0][tid] = 0.0f;         // h0 = 0

    // gi prefetch ring, distance 2 (3 gate rows per thread)
    const float* gbase = g_gi + (size_t)b * (T_ * G3_);
    float pr2[2], pz2[2], pn2[2];
    pr2[0] = gbase[j];                 pz2[0] = gbase[H_ + j];        pn2[0] = gbase[2 * H_ + j];
    pr2[1] = gbase[G3_ + j];           pz2[1] = gbase[G3_ + H_ + j];  pn2[1] = gbase[G3_ + 2 * H_ + j];

    __syncthreads();

    int p = 0;
    for (int t = 0; t < T_; t++) {
        const float gir = pr2[t & 1];
        const float giz = pz2[t & 1];
        const float gin = pn2[t & 1];
        const int tn = t + 2;
        if (tn < T_) {
            const float* gnx = gbase + tn * G3_;
            pr2[t & 1] = gnx[j];
            pz2[t & 1] = gnx[H_ + j];
            pn2[t & 1] = gnx[2 * H_ + j];
        }

        // matvec partials over this thread's 32 k-values (16 f32x2 per gate)
        const ulonglong2* h4 = reinterpret_cast<const ulonglong2*>(hbuf[p]) + s * 8;
        u64 ar0 = pk2(0.0f, 0.0f), ar1 = pk2(0.0f, 0.0f);
        u64 az0 = pk2(0.0f, 0.0f), az1 = pk2(0.0f, 0.0f);
        u64 an0 = pk2(bhn,  0.0f), an1 = pk2(0.0f, 0.0f);
        #pragma unroll
        for (int m = 0; m < 4; m++) {
            ulonglong2 v0 = h4[2 * m + 0];
            ulonglong2 v1 = h4[2 * m + 1];
            ar0 = fma2(wr_[4 * m + 0], v0.x, ar0);
            az0 = fma2(wz_[4 * m + 0], v0.x, az0);
            an0 = fma2(wn_[4 * m + 0], v0.x, an0);
            ar1 = fma2(wr_[4 * m + 1], v0.y, ar1);
            az1 = fma2(wz_[4 * m + 1], v0.y, az1);
            an1 = fma2(wn_[4 * m + 1], v0.y, an1);
            ar0 = fma2(wr_[4 * m + 2], v1.x, ar0);
            az0 = fma2(wz_[4 * m + 2], v1.x, az0);
            an0 = fma2(wn_[4 * m + 2], v1.x, an0);
            ar1 = fma2(wr_[4 * m + 3], v1.y, ar1);
            az1 = fma2(wz_[4 * m + 3], v1.y, az1);
            an1 = fma2(wn_[4 * m + 3], v1.y, an1);
        }
        // combine chains, then combine k-halves via bfly(16) — both halves get the sum
        u64 sr = add2(ar0, ar1);
        u64 sz = add2(az0, az1);
        u64 sn = add2(an0, an1);
        sr = add2(sr, shflx16(sr));
        sz = add2(sz, shflx16(sz));
        sn = add2(sn, shflx16(sn));
        const float hr = red2(sr);
        const float hz = red2(sz);
        const float hn = red2(sn);

        // full gate math local to the unit-owning thread (redundant on both halves)
        const float r    = sigmoidf_(gir + hr);
        const float z    = sigmoidf_(giz + hz);
        const float n    = tanhf_(gin + r * hn);
        const float hold = hbuf[p][j];
        const float hnew = n + z * (hold - n);     // (1-z)*n + z*h

        if (s == 0) hbuf[1 - p][j] = hnew;
        __syncthreads();                           // single barrier per step
        p ^= 1;
    }

    // linear head: h_T is in hbuf[0] (T even)
    if (tid < H_) sred[tid] = hbuf[0][tid] * fc_w[tid];
    __syncthreads();
    if (tid == 0) {
        float acc = fc_b[0];
        #pragma unroll
        for (int k = 0; k < H_; k++) acc += sred[k];
        out[b] = acc;
    }
}

extern "C" void kernel_launch(void* const* d_in, const int* in_sizes, int n_in,
                              void* d_out, int out_size) {
    const float* x    = (const float*)d_in[0];
    const float* w_ih = (const float*)d_in[1];
    const float* w_hh = (const float*)d_in[2];
    const float* b_ih = (const float*)d_in[3];
    const float* b_hh = (const float*)d_in[4];
    const float* fc_w = (const float*)d_in[5];
    const float* fc_b = (const float*)d_in[6];
    float* out = (float*)d_out;

    gru_xproj_kernel<<<B_, G3_>>>(x, w_ih, b_ih, b_hh);
    gru_rec_kernel<<<B_, NT2>>>(w_hh, b_hh, fc_w, fc_b, out);
}

// round 6
// speedup vs baseline: 1.7099x; 1.1061x over previous
#include <cuda_runtime.h>

typedef unsigned long long u64;

#define B_ 4096
#define T_ 128
#define I_ 16
#define H_ 64
#define G3_ 192
#define NB 4      // batches per rec CTA (and per thread)
#define NTR 128   // rec threads: 4 warps; thread = (unit-pair p, k-quarter q)

// 402 MB scratch: gi2[b][t][p(32)][slot(6)], slot = gate*2 + (unit>=32)
__device__ float g_gi[(size_t)B_ * T_ * G3_];

// ---- packed f32x2 helpers ----
__device__ __forceinline__ u64 pk2(float lo, float hi) {
    u64 r; asm("mov.b64 %0, {%1,%2};" : "=l"(r) : "f"(lo), "f"(hi)); return r;
}
__device__ __forceinline__ void upk2(u64 v, float& lo, float& hi) {
    asm("mov.b64 {%0,%1}, %2;" : "=f"(lo), "=f"(hi) : "l"(v));
}
__device__ __forceinline__ u64 fma2(u64 a, u64 b, u64 c) {
    u64 d; asm("fma.rn.f32x2 %0, %1, %2, %3;" : "=l"(d) : "l"(a), "l"(b), "l"(c)); return d;
}
__device__ __forceinline__ u64 add2(u64 a, u64 b) {
    u64 d; asm("add.rn.f32x2 %0, %1, %2;" : "=l"(d) : "l"(a), "l"(b)); return d;
}
__device__ __forceinline__ float red2(u64 v) { float lo, hi; upk2(v, lo, hi); return lo + hi; }

__device__ __forceinline__ float sigmoidf_(float a) { return __fdividef(1.0f, 1.0f + __expf(-a)); }
__device__ __forceinline__ float tanhf_(float a)    { return __fdividef(2.0f, 1.0f + __expf(-2.0f * a)) - 1.0f; }

// select sf[q] with 3 SELs (q is runtime-uniform per lane group)
__device__ __forceinline__ float selq(float a, float b, float c, float d, int q) {
    float x01 = (q & 1) ? b : a;
    float x23 = (q & 1) ? d : c;
    return (q & 2) ? x23 : x01;
}

// ============================================================================
// Pass 1: gi2[b][t][p][slot] = w_ih[g,:]·x[b,t,:] + b_ih[g] (+ b_hh[g] for r/z)
// thread tid -> (p = tid/6, slot = tid%6); g = gate*64 + hi*32 + p
// ============================================================================
__global__ __launch_bounds__(G3_) void gru_xproj_kernel(
    const float* __restrict__ x,     // [B, T, I]
    const float* __restrict__ w_ih,  // [3H, I]
    const float* __restrict__ b_ih,  // [3H]
    const float* __restrict__ b_hh)  // [3H]
{
    __shared__ __align__(16) u64 sx[T_ * I_ / 2];   // 8 KB
    const int tid = threadIdx.x;
    const int b   = blockIdx.x;
    const int p    = tid / 6;
    const int slot = tid - p * 6;
    const int gate = slot >> 1;
    const int hi   = slot & 1;
    const int g    = gate * H_ + hi * 32 + p;       // gate row in [0,192)

    const u64* gx = reinterpret_cast<const u64*>(x + (size_t)b * (T_ * I_));
    for (int i = tid; i < T_ * I_ / 2; i += G3_) sx[i] = gx[i];

    u64 wi[I_ / 2];
    const u64* wr = reinterpret_cast<const u64*>(w_ih + g * I_);
    #pragma unroll
    for (int k = 0; k < I_ / 2; k++) wi[k] = wr[k];
    const float bias = b_ih[g] + ((gate < 2) ? b_hh[g] : 0.0f);

    __syncthreads();

    float* gout = g_gi + (size_t)b * (T_ * G3_) + tid;   // tid == p*6+slot: coalesced
    #pragma unroll 4
    for (int t = 0; t < T_; t++) {
        const ulonglong2* xt = reinterpret_cast<const ulonglong2*>(sx + t * (I_ / 2));
        u64 a0 = pk2(bias, 0.0f), a1 = pk2(0.0f, 0.0f);
        #pragma unroll
        for (int m = 0; m < I_ / 4; m++) {
            ulonglong2 v = xt[m];
            a0 = fma2(wi[2 * m + 0], v.x, a0);
            a1 = fma2(wi[2 * m + 1], v.y, a1);
        }
        gout[t * G3_] = red2(add2(a0, a1));
    }
}

// ============================================================================
// Pass 2: recurrence, NB=4 batches per thread over shared weight registers.
// ============================================================================
__global__ void __launch_bounds__(NTR, 2) gru_rec_kernel(
    const float* __restrict__ w_hh,  // [3H, H]
    const float* __restrict__ b_hh,  // [3H]
    const float* __restrict__ fc_w,  // [1, H]
    const float* __restrict__ fc_b,  // [1]
    float* __restrict__ out)         // [B]
{
    __shared__ __align__(16) float hbuf[NB][2][H_];   // 2 KB double-buffered h

    const int tid  = threadIdx.x;
    const int lane = tid & 31;
    const int w    = tid >> 5;          // warp 0..3
    const int q    = (lane >> 3) & 3;   // k-quarter AND owned batch index
    const int p    = w * 8 + (lane & 7);// unit pair 0..31
    const int j0   = p, j1 = p + 32;
    const int bBase = blockIdx.x * NB;

    // weights: rows [j0, j1, j0+64, j1+64, j0+128, j1+128], cols [16q,16q+16)
    u64 wv[6][8];                       // 48 u64 = 96 regs
    {
        const int rows[6] = { j0, j1, j0 + H_, j1 + H_, j0 + 2 * H_, j1 + 2 * H_ };
        #pragma unroll
        for (int r = 0; r < 6; r++) {
            const u64* src = reinterpret_cast<const u64*>(w_hh + rows[r] * H_ + q * 16);
            #pragma unroll
            for (int m = 0; m < 8; m++) wv[r][m] = src[m];
        }
    }
    const float bhn0 = b_hh[j0 + 2 * H_];
    const float bhn1 = b_hh[j1 + 2 * H_];

    // zero hbuf[*][0][*]
    #pragma unroll
    for (int k = tid; k < NB * H_; k += NTR)
        reinterpret_cast<float*>(hbuf)[(k >> 6) * (2 * H_) + (k & 63)] = 0.0f;

    // gi ring (distance 1), batch q only: 3 u64 per step at p*6
    const u64* gp = reinterpret_cast<const u64*>(
        g_gi + ((size_t)(bBase + q) * T_) * G3_ + p * 6);
    u64 c0 = gp[0], c1 = gp[1], c2 = gp[2];
    gp += G3_ / 2;

    float h0 = 0.0f, h1 = 0.0f;         // register-carried h for (q, j0/j1)

    __syncthreads();

    for (int t = 0; t < T_; t++) {
        // prefetch gi for t+1
        u64 n0, n1, n2;
        if (t < T_ - 1) { n0 = gp[0]; n1 = gp[1]; n2 = gp[2]; gp += G3_ / 2; }

        // ---- matvec partials: 4 batches x 6 rows x 8 FFMA2 ----
        u64 acc[NB][6];
        #pragma unroll
        for (int i = 0; i < NB; i++) {
            const ulonglong2* hp =
                reinterpret_cast<const ulonglong2*>(hbuf[i][t & 1]) + q * 4;
            ulonglong2 v0 = hp[0], v1 = hp[1], v2 = hp[2], v3 = hp[3];
            u64 hv0 = v0.x, hv1 = v0.y, hv2 = v1.x, hv3 = v1.y;
            u64 hv4 = v2.x, hv5 = v2.y, hv6 = v3.x, hv7 = v3.y;
            #pragma unroll
            for (int r = 0; r < 6; r++) {
                u64 a = fma2(wv[r][0], hv0, pk2(0.0f, 0.0f));
                a = fma2(wv[r][1], hv1, a);
                a = fma2(wv[r][2], hv2, a);
                a = fma2(wv[r][3], hv3, a);
                a = fma2(wv[r][4], hv4, a);
                a = fma2(wv[r][5], hv5, a);
                a = fma2(wv[r][6], hv6, a);
                a = fma2(wv[r][7], hv7, a);
                acc[i][r] = a;
            }
        }

        // ---- reduce across k-quarters: red2 then butterfly xor8, xor16 ----
        float sf[NB][6];
        #pragma unroll
        for (int i = 0; i < NB; i++)
            #pragma unroll
            for (int r = 0; r < 6; r++) sf[i][r] = red2(acc[i][r]);
        #pragma unroll
        for (int i = 0; i < NB; i++)
            #pragma unroll
            for (int r = 0; r < 6; r++)
                sf[i][r] += __shfl_xor_sync(0xFFFFFFFFu, sf[i][r], 8);
        #pragma unroll
        for (int i = 0; i < NB; i++)
            #pragma unroll
            for (int r = 0; r < 6; r++)
                sf[i][r] += __shfl_xor_sync(0xFFFFFFFFu, sf[i][r], 16);

        // ---- this lane finishes batch q, units j0/j1 ----
        const float hr0 = selq(sf[0][0], sf[1][0], sf[2][0], sf[3][0], q);
        const float hr1 = selq(sf[0][1], sf[1][1], sf[2][1], sf[3][1], q);
        const float hz0 = selq(sf[0][2], sf[1][2], sf[2][2], sf[3][2], q);
        const float hz1 = selq(sf[0][3], sf[1][3], sf[2][3], sf[3][3], q);
        const float hn0 = selq(sf[0][4], sf[1][4], sf[2][4], sf[3][4], q);
        const float hn1 = selq(sf[0][5], sf[1][5], sf[2][5], sf[3][5], q);

        float gir0, gir1, giz0, giz1, gin0, gin1;
        upk2(c0, gir0, gir1);
        upk2(c1, giz0, giz1);
        upk2(c2, gin0, gin1);

        const float r0 = sigmoidf_(gir0 + hr0);
        const float r1 = sigmoidf_(gir1 + hr1);
        const float z0 = sigmoidf_(giz0 + hz0);
        const float z1 = sigmoidf_(giz1 + hz1);
        const float nn0 = tanhf_(gin0 + r0 * (hn0 + bhn0));
        const float nn1 = tanhf_(gin1 + r1 * (hn1 + bhn1));
        h0 = nn0 + z0 * (h0 - nn0);
        h1 = nn1 + z1 * (h1 - nn1);

        hbuf[q][(t + 1) & 1][j0] = h0;
        hbuf[q][(t + 1) & 1][j1] = h1;

        c0 = n0; c1 = n1; c2 = n2;
        __syncthreads();                 // one barrier per step
    }

    // ---- head: warp w reduces batch w (h_T is in hbuf[i][0], T even) ----
    float v = hbuf[w][0][lane] * fc_w[lane] + hbuf[w][0][lane + 32] * fc_w[lane + 32];
    #pragma unroll
    for (int o = 16; o > 0; o >>= 1) v += __shfl_xor_sync(0xFFFFFFFFu, v, o);
    if (lane == 0) out[bBase + w] = v + fc_b[0];
}

extern "C" void kernel_launch(void* const* d_in, const int* in_sizes, int n_in,
                              void* d_out, int out_size) {
    const float* x    = (const float*)d_in[0];
    const float* w_ih = (const float*)d_in[1];
    const float* w_hh = (const float*)d_in[2];
    const float* b_ih = (const float*)d_in[3];
    const float* b_hh = (const float*)d_in[4];
    const float* fc_w = (const float*)d_in[5];
    const float* fc_b = (const float*)d_in[6];
    float* out = (float*)d_out;

    gru_xproj_kernel<<<B_, G3_>>>(x, w_ih, b_ih, b_hh);
    gru_rec_kernel<<<B_ / NB, NTR>>>(w_hh, b_hh, fc_w, fc_b, out);
}

// round 8
// speedup vs baseline: 2.0267x; 1.1853x over previous
#include <cuda_runtime.h>

typedef unsigned long long u64;

#define B_ 4096
#define T_ 128
#define I_ 16
#define H_ 64
#define NB 4      // batches per CTA
#define NTR 128   // 4 warps; thread = (unit j = w*16+(lane&15), k-half s = lane>>4)

// ---- packed f32x2 helpers (sm_100+; ptxas never emits these from C++) ----
__device__ __forceinline__ u64 pk2(float lo, float hi) {
    u64 r; asm("mov.b64 %0, {%1,%2};" : "=l"(r) : "f"(lo), "f"(hi)); return r;
}
__device__ __forceinline__ void upk2(u64 v, float& lo, float& hi) {
    asm("mov.b64 {%0,%1}, %2;" : "=f"(lo), "=f"(hi) : "l"(v));
}
__device__ __forceinline__ u64 fma2(u64 a, u64 b, u64 c) {
    u64 d; asm("fma.rn.f32x2 %0, %1, %2, %3;" : "=l"(d) : "l"(a), "l"(b), "l"(c)); return d;
}
__device__ __forceinline__ u64 add2(u64 a, u64 b) {
    u64 d; asm("add.rn.f32x2 %0, %1, %2;" : "=l"(d) : "l"(a), "l"(b)); return d;
}
__device__ __forceinline__ float red2(u64 v) { float lo, hi; upk2(v, lo, hi); return lo + hi; }

// exp-based activations (~1e-6/step; tanh.approx's 2^-11 would compound over T=128)
__device__ __forceinline__ float sigmoidf_(float a) { return __fdividef(1.0f, 1.0f + __expf(-a)); }
__device__ __forceinline__ float tanhf_(float a)    { return __fdividef(2.0f, 1.0f + __expf(-2.0f * a)) - 1.0f; }

__global__ void __launch_bounds__(NTR, 3) gru_fused_kernel(
    const float* __restrict__ x,     // [B, T, I]
    const float* __restrict__ w_ih,  // [3H, I]
    const float* __restrict__ w_hh,  // [3H, H]
    const float* __restrict__ b_ih,  // [3H]
    const float* __restrict__ b_hh,  // [3H]
    const float* __restrict__ fc_w,  // [1, H]
    const float* __restrict__ fc_b,  // [1]
    float* __restrict__ out)         // [B]
{
    __shared__ __align__(16) float sx[NB][T_][I_];     // 32 KB: x for 4 batches
    __shared__ __align__(16) float hbuf[NB][2][H_];    // 2 KB: double-buffered h

    const int tid  = threadIdx.x;
    const int lane = tid & 31;
    const int w    = tid >> 5;
    const int j    = w * 16 + (lane & 15);   // hidden unit 0..63
    const int s    = lane >> 4;              // k-half
    const int bBase = blockIdx.x * NB;

    // ---- register-resident weights: rows (j, j+64, j+128), k-cols [32s,32s+32) ----
    u64 whr[16], whz[16], whn[16];           // 48 u64 = 96 regs
    {
        const u64* pr = reinterpret_cast<const u64*>(w_hh + (j          ) * H_ + s * 32);
        const u64* pz = reinterpret_cast<const u64*>(w_hh + (j +     H_ ) * H_ + s * 32);
        const u64* pn = reinterpret_cast<const u64*>(w_hh + (j + 2 * H_ ) * H_ + s * 32);
        #pragma unroll
        for (int k = 0; k < 16; k++) { whr[k] = pr[k]; whz[k] = pz[k]; whn[k] = pn[k]; }
    }
    u64 wir[4], wiz[4], win[4];              // 12 u64 = 24 regs, x-cols [8s,8s+8)
    {
        const u64* qr = reinterpret_cast<const u64*>(w_ih + (j          ) * I_ + s * 8);
        const u64* qz = reinterpret_cast<const u64*>(w_ih + (j +     H_ ) * I_ + s * 8);
        const u64* qn = reinterpret_cast<const u64*>(w_ih + (j + 2 * H_ ) * I_ + s * 8);
        #pragma unroll
        for (int k = 0; k < 4; k++) { wir[k] = qr[k]; wiz[k] = qz[k]; win[k] = qn[k]; }
    }
    // biases injected once (s==0 accumulators); full value appears after butterfly
    const float bias_r  = s ? 0.0f : b_ih[j]          + b_hh[j];
    const float bias_z  = s ? 0.0f : b_ih[j + H_]     + b_hh[j + H_];
    const float bias_nx = s ? 0.0f : b_ih[j + 2 * H_];
    const float bias_nh = s ? 0.0f : b_hh[j + 2 * H_];

    // ---- preload x for NB batches (coalesced, 32 KB) ----
    {
        const u64* gx = reinterpret_cast<const u64*>(x + (size_t)bBase * (T_ * I_));
        u64* sxu = reinterpret_cast<u64*>(sx);
        #pragma unroll 4
        for (int i = tid; i < NB * T_ * I_ / 2; i += NTR) sxu[i] = gx[i];
    }
    for (int k = tid; k < NB * H_; k += NTR) hbuf[k >> 6][0][k & 63] = 0.0f;
    __syncthreads();

    for (int t = 0; t < T_; t++) {
        const int par = t & 1;
        float fr[NB], fz[NB], fnx[NB], fnh[NB];

        #pragma unroll
        for (int i = 0; i < NB; i++) {
            const ulonglong2* hp = reinterpret_cast<const ulonglong2*>(hbuf[i][par]) + s * 8;
            const ulonglong2* xp = reinterpret_cast<const ulonglong2*>(sx[i][t]) + s * 2;
            // x-part (8 floats = 4 u64)
            ulonglong2 xv0 = xp[0], xv1 = xp[1];
            u64 ar0 = pk2(bias_r,  0.0f), ar1 = pk2(0.0f, 0.0f);
            u64 az0 = pk2(bias_z,  0.0f), az1 = pk2(0.0f, 0.0f);
            u64 ah0 = pk2(bias_nh, 0.0f), ah1 = pk2(0.0f, 0.0f);
            u64 ax  = pk2(bias_nx, 0.0f);
            ar0 = fma2(wir[0], xv0.x, ar0); ar1 = fma2(wir[1], xv0.y, ar1);
            ar0 = fma2(wir[2], xv1.x, ar0); ar1 = fma2(wir[3], xv1.y, ar1);
            az0 = fma2(wiz[0], xv0.x, az0); az1 = fma2(wiz[1], xv0.y, az1);
            az0 = fma2(wiz[2], xv1.x, az0); az1 = fma2(wiz[3], xv1.y, az1);
            ax  = fma2(win[0], xv0.x, ax);  ax  = fma2(win[1], xv0.y, ax);
            ax  = fma2(win[2], xv1.x, ax);  ax  = fma2(win[3], xv1.y, ax);
            // h-part (32 floats = 16 u64, 8 LDS.128)
            #pragma unroll
            for (int m = 0; m < 4; m++) {
                ulonglong2 v0 = hp[2 * m + 0];
                ulonglong2 v1 = hp[2 * m + 1];
                ar0 = fma2(whr[4 * m + 0], v0.x, ar0);
                az0 = fma2(whz[4 * m + 0], v0.x, az0);
                ah0 = fma2(whn[4 * m + 0], v0.x, ah0);
                ar1 = fma2(whr[4 * m + 1], v0.y, ar1);
                az1 = fma2(whz[4 * m + 1], v0.y, az1);
                ah1 = fma2(whn[4 * m + 1], v0.y, ah1);
                ar0 = fma2(whr[4 * m + 2], v1.x, ar0);
                az0 = fma2(whz[4 * m + 2], v1.x, az0);
                ah0 = fma2(whn[4 * m + 2], v1.x, ah0);
                ar1 = fma2(whr[4 * m + 3], v1.y, ar1);
                az1 = fma2(whz[4 * m + 3], v1.y, az1);
                ah1 = fma2(whn[4 * m + 3], v1.y, ah1);
            }
            fr[i]  = red2(add2(ar0, ar1));
            fz[i]  = red2(add2(az0, az1));
            fnh[i] = red2(add2(ah0, ah1));
            fnx[i] = red2(ax);
        }

        // ---- combine k-halves: one scalar butterfly per reduced quantity ----
        #pragma unroll
        for (int i = 0; i < NB; i++) {
            fr[i]  += __shfl_xor_sync(0xFFFFFFFFu, fr[i],  16);
            fz[i]  += __shfl_xor_sync(0xFFFFFFFFu, fz[i],  16);
            fnx[i] += __shfl_xor_sync(0xFFFFFFFFu, fnx[i], 16);
            fnh[i] += __shfl_xor_sync(0xFFFFFFFFu, fnh[i], 16);
        }

        // ---- each k-half finishes 2 batches: activations + state update ----
        #pragma unroll
        for (int u = 0; u < 2; u++) {
            const int i = s * 2 + u;
            const float hold = hbuf[i][par][j];
            const float r = sigmoidf_(fr[i]);
            const float z = sigmoidf_(fz[i]);
            const float n = tanhf_(fnx[i] + r * fnh[i]);
            hbuf[i][par ^ 1][j] = n + z * (hold - n);
        }
        __syncthreads();                      // one barrier per step
    }

    // ---- head: warp w reduces batch w (final h in hbuf[i][0], T even) ----
    float v = hbuf[w][0][lane] * fc_w[lane] + hbuf[w][0][lane + 32] * fc_w[lane + 32];
    #pragma unroll
    for (int o = 16; o > 0; o >>= 1) v += __shfl_xor_sync(0xFFFFFFFFu, v, o);
    if (lane == 0) out[bBase + w] = v + fc_b[0];
}

extern "C" void kernel_launch(void* const* d_in, const int* in_sizes, int n_in,
                              void* d_out, int out_size) {
    const float* x    = (const float*)d_in[0];
    const float* w_ih = (const float*)d_in[1];
    const float* w_hh = (const float*)d_in[2];
    const float* b_ih = (const float*)d_in[3];
    const float* b_hh = (const float*)d_in[4];
    const float* fc_w = (const float*)d_in[5];
    const float* fc_b = (const float*)d_in[6];
    float* out = (float*)d_out;

    gru_fused_kernel<<<B_ / NB, NTR>>>(x, w_ih, w_hh, b_ih, b_hh, fc_w, fc_b, out);
}